// round 15
// baseline (speedup 1.0000x reference)
#include <cuda_runtime.h>
#include <cuda_fp16.h>
#include <cstdint>

// Shapes fixed: B=16, N=64, D=E=256. Output: [new_nodes 1024x256 | h 65536x256] f32.
#define NROWS     1024
#define OUT_H_OFF (NROWS * 256)

// ---------------- device scratch ----------------
__device__ float    g_PQ[NROWS * 512];    // P = nodes@W1 + b_in | Q = nodes@W2
__device__ uint32_t g_W3n[256 * 128];     // W3 fp16, N-MAJOR: [n][kp], u32 = halves {2kp,2kp+1}
__device__ float    g_res[NROWS * 256];   // attn-weighted residual
__device__ float    g_sink[256];          // prefetch sink

// ---------------- helpers ----------------
__device__ __forceinline__ uint32_t pack2h(float lo, float hi) {
    __half2 h = __floats2half2_rn(lo, hi);
    return *(uint32_t*)&h;
}
__device__ __forceinline__ void mma_f16(float* c, const uint32_t* a, const uint32_t* b) {
    asm volatile(
        "mma.sync.aligned.m16n8k16.row.col.f32.f16.f16.f32 "
        "{%0,%1,%2,%3}, {%4,%5,%6,%7}, {%8,%9}, {%0,%1,%2,%3};"
        : "+f"(c[0]), "+f"(c[1]), "+f"(c[2]), "+f"(c[3])
        : "r"(a[0]), "r"(a[1]), "r"(a[2]), "r"(a[3]), "r"(b[0]), "r"(b[1]));
}
__device__ __forceinline__ void ldsm_x4(uint32_t& r0, uint32_t& r1, uint32_t& r2, uint32_t& r3,
                                        uint32_t addr) {
    asm volatile("ldmatrix.sync.aligned.m8n8.x4.shared.b16 {%0,%1,%2,%3}, [%4];"
                 : "=r"(r0), "=r"(r1), "=r"(r2), "=r"(r3) : "r"(addr));
}
__device__ __forceinline__ uint32_t smem_u32(const void* p) {
    uint32_t a;
    asm("{ .reg .u64 t; cvta.to.shared.u64 t, %1; cvt.u32.u64 %0, t; }" : "=r"(a) : "l"(p));
    return a;
}
#define CP_ASYNC16(dst, src) \
    asm volatile("cp.async.cg.shared.global [%0], [%1], 16;" :: "r"(dst), "l"(src))
#define CP_COMMIT()  asm volatile("cp.async.commit_group;" ::: "memory")
#define CP_WAIT1()   asm volatile("cp.async.wait_group 1;" ::: "memory")
#define CP_WAIT0()   asm volatile("cp.async.wait_group 0;" ::: "memory")

// ---------------- smem layout for gnn_main8 (bytes) ----------------
// E tile fp16 [64 rows][40 halves] (stride 80B, ldmatrix-clean) = 5120
// W bufs fp16 n-major [256 n][40 halves] (stride 80B) = 20480 each
#define ESM_OFF   0        // 5120
#define WC0_OFF   5120     // -> 25600
#define WC1_OFF   25600    // -> 46080
#define HS_OFF    0        // epilogue overlay [64][260] f = 66560
#define PS_OFF    66560    // 256 f
#define WCS_OFF   67584    // 256 f
#define CP_OFF    68608    // [4][64] f
#define COEF_OFF  69632    // 64 f
#define ATTN_OFF  69888    // 64 f
#define SMEM_BYTES 70144

// ===========================================================================
// Kernel A1: PQ = [nodes@W1 + b_in | nodes@W2], 32x64 tiles. grid 256 x 256.
// ===========================================================================
__global__ __launch_bounds__(256) void prep_pq(
    const float* __restrict__ nodes, const float* __restrict__ W_in, const float* __restrict__ b_in)
{
    __shared__ float smbuf[64 * 36 + 64 * 64];
    float* As = smbuf;
    float* Bs = smbuf + 64 * 36;
    const int tid = threadIdx.x;
    const int cb = blockIdx.x & 7;
    const int rb = blockIdx.x >> 3;
    const int kadd = (cb >= 4) ? 256 : 0;
    const int cbase = (cb & 3) * 64;
    const int ty = tid >> 5;
    const int tx = tid & 31;

    float4 apf[2], bpf[4];
    auto loadA = [&](int kc) {
#pragma unroll
        for (int u = 0; u < 2; ++u) {
            int idx = tid * 2 + u;
            int r = idx >> 4, k4 = (idx & 15) << 2;
            apf[u] = *(const float4*)(nodes + (size_t)(rb * 32 + r) * 256 + kc * 64 + k4);
        }
    };
    auto loadB = [&](int kc) {
#pragma unroll
        for (int u = 0; u < 4; ++u) {
            int idx = tid + u * 256;
            int k = idx >> 4, c4 = (idx & 15) << 2;
            bpf[u] = *(const float4*)(W_in + (size_t)(kadd + kc * 64 + k) * 256 + cbase + c4);
        }
    };

    float acc[4][2];
#pragma unroll
    for (int a = 0; a < 4; ++a) { acc[a][0] = 0.f; acc[a][1] = 0.f; }

    loadA(0);
    loadB(0);

    for (int kc = 0; kc < 4; ++kc) {
#pragma unroll
        for (int u = 0; u < 2; ++u) {
            int idx = tid * 2 + u, r = idx >> 4, k4 = (idx & 15) << 2;
            As[(k4 + 0) * 36 + r] = apf[u].x; As[(k4 + 1) * 36 + r] = apf[u].y;
            As[(k4 + 2) * 36 + r] = apf[u].z; As[(k4 + 3) * 36 + r] = apf[u].w;
        }
#pragma unroll
        for (int u = 0; u < 4; ++u) {
            int idx = tid + u * 256, k = idx >> 4, c4 = (idx & 15) << 2;
            *(float4*)(Bs + k * 64 + c4) = bpf[u];
        }
        __syncthreads();

        if (kc < 3) { loadA(kc + 1); loadB(kc + 1); }

#pragma unroll 8
        for (int kk = 0; kk < 64; ++kk) {
            float4 av = *(const float4*)(As + kk * 36 + ty * 4);
            float2 bv = *(const float2*)(Bs + kk * 64 + tx * 2);
            acc[0][0] += av.x * bv.x; acc[0][1] += av.x * bv.y;
            acc[1][0] += av.y * bv.x; acc[1][1] += av.y * bv.y;
            acc[2][0] += av.z * bv.x; acc[2][1] += av.z * bv.y;
            acc[3][0] += av.w * bv.x; acc[3][1] += av.w * bv.y;
        }
        __syncthreads();
    }

    float2 bias = make_float2(0.f, 0.f);
    if (cb < 4) bias = *(const float2*)(b_in + cbase + tx * 2);
#pragma unroll
    for (int ri = 0; ri < 4; ++ri) {
        int r = rb * 32 + ty * 4 + ri;
        *(float2*)(g_PQ + (size_t)r * 512 + cb * 64 + tx * 2) =
            make_float2(acc[ri][0] + bias.x, acc[ri][1] + bias.y);
    }
}

// ===========================================================================
// Kernel A2: W3 [k][n] f32 -> g_W3n [n][kp] packed fp16 (transpose+convert).
// grid (8,8) x 256: kb = by*32, nb = bx*32.
// ===========================================================================
__global__ __launch_bounds__(256) void conv_w3(const float* __restrict__ W_in)
{
    __shared__ float t[32][33];
    const float* W3 = W_in + (size_t)512 * 256;
    const int bx = blockIdx.x, by = blockIdx.y;
    const int tx = threadIdx.x & 31, ty = threadIdx.x >> 5;
#pragma unroll
    for (int u = 0; u < 32; u += 8)
        t[ty + u][tx] = W3[(size_t)(by * 32 + ty + u) * 256 + bx * 32 + tx];
    __syncthreads();

    const int kp = threadIdx.x & 15;        // 0..15 (k-pair within block)
    const int nn = threadIdx.x >> 4;        // 0..15
#pragma unroll
    for (int v = 0; v < 2; ++v) {
        int n = nn + v * 16;
        uint32_t val = pack2h(t[2 * kp][n], t[2 * kp + 1][n]);
        g_W3n[(size_t)(bx * 32 + n) * 128 + by * 16 + kp] = val;
    }
}

// ===========================================================================
// Kernel A3: edge L2 prefetch; also keeps gnn at ncu capture slot 4.
// ===========================================================================
__global__ __launch_bounds__(256) void prefetch_edges(const float* __restrict__ edges)
{
    float s = 0.f;
    const float* p = edges + (size_t)blockIdx.x * 64 * 256;
#pragma unroll
    for (int u = 0; u < 4; ++u) {
        float4 v = *(const float4*)(p + (u * 256 + threadIdx.x) * 16);
        s += v.x + v.y + v.z + v.w;
    }
    if (s == 1.0e38f) g_sink[threadIdx.x] = s;
}

// ===========================================================================
// Kernel B: fp16 m16n8k16 mma + fused attention. Fragments via ldmatrix.x4
// (A: 2/step, B: 4/step vs 24 scalar LDS). W n-major [256][40h], stride 80B.
// Fragment VALUES identical to R13 -> same numerics.
// ===========================================================================
__global__ __launch_bounds__(256) void gnn_main8(
    const float* __restrict__ edges,
    const float* __restrict__ W_coef,
    float* __restrict__ out)
{
    extern __shared__ char sm[];
    const uint32_t sbase = smem_u32(sm);
    float* hs   = (float*)(sm + HS_OFF);
    float* ps   = (float*)(sm + PS_OFF);
    float* wcs  = (float*)(sm + WCS_OFF);
    float* cp   = (float*)(sm + CP_OFF);
    float* coef_s = (float*)(sm + COEF_OFF);
    float* attn_s = (float*)(sm + ATTN_OFF);

    const int tid = threadIdx.x;
    const int wid = tid >> 5;
    const int l   = tid & 31;
    const int mw  = wid >> 2;
    const int nw  = wid & 3;
    const int rg  = l >> 2;
    const int tg  = l & 3;
    const int bid = blockIdx.x;
    const int b64 = (bid >> 6) << 6;
    const int i_g = bid & 63;

    ps[tid]  = g_PQ[(size_t)bid * 512 + tid];
    wcs[tid] = W_coef[tid];

    const float* Ebase = edges + (size_t)bid * 64 * 256;

    // ---- E staging: LDG float4 x2 -> 4x f16x2 -> one STS.128 ----
    const int er = tid >> 2;              // row 0..63
    const int ek = (tid & 3) * 8;         // halves offset
    float4 epf0, epf1;
    auto loadE = [&](int ch) {
        const float* p = Ebase + (size_t)er * 256 + ch * 32 + ek;
        epf0 = *(const float4*)p;
        epf1 = *(const float4*)(p + 4);
    };
    auto stsE = [&]() {
        uint4 u;
        u.x = pack2h(epf0.x, epf0.y);
        u.y = pack2h(epf0.z, epf0.w);
        u.z = pack2h(epf1.x, epf1.y);
        u.w = pack2h(epf1.z, epf1.w);
        *(uint4*)(sm + ESM_OFF + er * 80 + ek * 2) = u;
    };

    // ---- W staging: cp.async 16B, tile [256 n][32 halves] at stride 80B ----
    auto stageW = [&](int ch, int buf) {
        uint32_t w_dst = sbase + (buf ? WC1_OFF : WC0_OFF);
#pragma unroll
        for (int u = 0; u < 4; ++u) {
            int idx = tid + u * 256;              // 0..1023
            int n = idx >> 2, seg = idx & 3;
            CP_ASYNC16(w_dst + (uint32_t)(n * 80 + seg * 16),
                       g_W3n + (size_t)n * 128 + ch * 16 + seg * 4);
        }
    };

    // ---- ldmatrix lane addresses (byte offsets, precomputed) ----
    const int lrow8 = (l & 7) + ((l >> 3) & 1) * 8;   // row within 16-row tile
    const int lkoff = ((l >> 4) & 1) * 16;            // k byte offset (8 halves)
    uint32_t aBase[2];
#pragma unroll
    for (int mt = 0; mt < 2; ++mt)
        aBase[mt] = sbase + ESM_OFF + (uint32_t)(mw * 32 + mt * 16 + lrow8) * 80 + lkoff;
    uint32_t bBase[4];
#pragma unroll
    for (int ntp = 0; ntp < 4; ++ntp)
        bBase[ntp] = (uint32_t)(nw * 64 + ntp * 16 + lrow8) * 80 + lkoff;

    float acc[2][8][4];
#pragma unroll
    for (int mt = 0; mt < 2; ++mt)
#pragma unroll
        for (int nt = 0; nt < 8; ++nt)
#pragma unroll
            for (int q = 0; q < 4; ++q) acc[mt][nt][q] = 0.f;

    loadE(0);
    stageW(0, 0);
    CP_COMMIT();

    for (int ch = 0; ch < 8; ++ch) {
        stsE();
        if (ch < 7) {
            stageW(ch + 1, (ch + 1) & 1);
            CP_COMMIT();
            CP_WAIT1();
        } else {
            CP_WAIT0();
        }
        __syncthreads();

        if (ch < 7) loadE(ch + 1);

        const uint32_t wbuf = sbase + ((ch & 1) ? WC1_OFF : WC0_OFF);

#pragma unroll
        for (int s = 0; s < 2; ++s) {
            const uint32_t sk = s * 32;           // 16 halves per step
            uint32_t a[2][4], b[8][2];
#pragma unroll
            for (int mt = 0; mt < 2; ++mt)
                ldsm_x4(a[mt][0], a[mt][1], a[mt][2], a[mt][3], aBase[mt] + sk);
#pragma unroll
            for (int ntp = 0; ntp < 4; ++ntp) {
                uint32_t t0, t1, t2, t3;
                ldsm_x4(t0, t1, t2, t3, wbuf + bBase[ntp] + sk);
                b[2 * ntp][0] = t0; b[2 * ntp + 1][0] = t1;
                b[2 * ntp][1] = t2; b[2 * ntp + 1][1] = t3;
            }
#pragma unroll
            for (int mt = 0; mt < 2; ++mt)
#pragma unroll
                for (int nt = 0; nt < 8; ++nt)
                    mma_f16(acc[mt][nt], a[mt], b[nt]);
        }
        __syncthreads();
    }

    // ---- epilogue: h = relu(acc + P_i + Q_j) -> hs (R13-exact) ----
#pragma unroll
    for (int mt = 0; mt < 2; ++mt) {
        int rA = mw * 32 + mt * 16 + rg;
        int rB = rA + 8;
        const float* qA = g_PQ + (size_t)(b64 + rA) * 512 + 256;
        const float* qB = g_PQ + (size_t)(b64 + rB) * 512 + 256;
#pragma unroll
        for (int nt = 0; nt < 8; ++nt) {
            int c0 = nw * 64 + nt * 8 + tg * 2;
            float2 pv = *(const float2*)(ps + c0);
            float2 qa = *(const float2*)(qA + c0);
            float2 qb = *(const float2*)(qB + c0);
            float h0 = fmaxf(acc[mt][nt][0] + pv.x + qa.x, 0.f);
            float h1 = fmaxf(acc[mt][nt][1] + pv.y + qa.y, 0.f);
            float h2 = fmaxf(acc[mt][nt][2] + pv.x + qb.x, 0.f);
            float h3 = fmaxf(acc[mt][nt][3] + pv.y + qb.y, 0.f);
            *(float2*)(hs + rA * 260 + c0) = make_float2(h0, h1);
            *(float2*)(hs + rB * 260 + c0) = make_float2(h2, h3);
        }
    }
    __syncthreads();

    // ---- h -> gmem ----
    float* hout = out + OUT_H_OFF + (size_t)bid * 64 * 256;
#pragma unroll
    for (int rr = wid * 8; rr < wid * 8 + 8; ++rr) {
#pragma unroll
        for (int q = 0; q < 2; ++q) {
            float4 v = *(const float4*)(hs + rr * 260 + q * 128 + l * 4);
            *(float4*)(hout + (size_t)rr * 256 + q * 128 + l * 4) = v;
        }
    }

    // ---- coef[j] = sum_d h[j][d] * wc[d] ----
    {
        int j = tid & 63, seg = tid >> 6;
        float s = 0.f;
#pragma unroll 8
        for (int d = 0; d < 64; ++d)
            s += hs[j * 260 + seg * 64 + d] * wcs[seg * 64 + d];
        cp[seg * 64 + j] = s;
    }
    __syncthreads();
    if (tid < 64)
        coef_s[tid] = cp[tid] + cp[64 + tid] + cp[128 + tid] + cp[192 + tid]
                    - ((tid == i_g) ? 1e9f : 0.f);
    __syncthreads();

    // ---- softmax ----
    float mval = -3.0e38f;
#pragma unroll 8
    for (int j = 0; j < 64; ++j) mval = fmaxf(mval, coef_s[j]);
    if (tid < 64) attn_s[tid] = __expf(coef_s[tid] - mval);
    __syncthreads();

    float ssum = 0.f;
#pragma unroll 8
    for (int j = 0; j < 64; ++j) ssum += attn_s[j];
    float inv = 1.f / ssum;

    // ---- residual ----
    float r = 0.f;
#pragma unroll 8
    for (int j = 0; j < 64; ++j)
        r += attn_s[j] * hs[j * 260 + tid];
    g_res[(size_t)bid * 256 + tid] = r * inv;
}

// ===========================================================================
// Kernel C: new_nodes = nodes + relu(g_res @ W_out + b_out). (unchanged)
// ===========================================================================
__global__ __launch_bounds__(256) void finalize3(
    const float* __restrict__ nodes, const float* __restrict__ W_out,
    const float* __restrict__ b_out, float* __restrict__ out)
{
    __shared__ float rs[8 * 256];
    __shared__ float red[8 * 128];
    const int tid = threadIdx.x;
    const int c0 = blockIdx.x * 128;
    const int r0 = blockIdx.y * 8;
    const int lc = tid & 127;
    const int c  = c0 + lc;
    const int kh = tid >> 7;

#pragma unroll
    for (int u = 0; u < 8; ++u)
        rs[u * 256 + tid] = g_res[(size_t)(r0 + u) * 256 + tid];
    __syncthreads();

    float acc[8];
#pragma unroll
    for (int q = 0; q < 8; ++q) acc[q] = 0.f;

    const int kbase = kh * 128;
    const float* Wp = W_out + (size_t)kbase * 256 + c;

#pragma unroll 8
    for (int k4 = 0; k4 < 32; ++k4) {
        float w0 = Wp[(size_t)(k4 * 4 + 0) * 256];
        float w1 = Wp[(size_t)(k4 * 4 + 1) * 256];
        float w2 = Wp[(size_t)(k4 * 4 + 2) * 256];
        float w3 = Wp[(size_t)(k4 * 4 + 3) * 256];
#pragma unroll
        for (int q = 0; q < 8; ++q) {
            float4 rv = *(const float4*)(rs + q * 256 + kbase + k4 * 4);
            acc[q] += rv.x * w0 + rv.y * w1 + rv.z * w2 + rv.w * w3;
        }
    }

    if (kh) {
#pragma unroll
        for (int q = 0; q < 8; ++q) red[q * 128 + lc] = acc[q];
    }
    __syncthreads();
    if (!kh) {
        float bo = b_out[c];
#pragma unroll
        for (int q = 0; q < 8; ++q) {
            float v = acc[q] + red[q * 128 + lc] + bo;
            out[(size_t)(r0 + q) * 256 + c] =
                nodes[(size_t)(r0 + q) * 256 + c] + fmaxf(v, 0.f);
        }
    }
}

// ===========================================================================
extern "C" void kernel_launch(void* const* d_in, const int* in_sizes, int n_in,
                              void* d_out, int out_size) {
    const float* nodes  = (const float*)d_in[0];
    const float* edges  = (const float*)d_in[1];
    const float* W_in   = (const float*)d_in[2];
    const float* b_in   = (const float*)d_in[3];
    const float* W_coef = (const float*)d_in[4];
    // d_in[5] = b_coef: softmax-invariant, skipped
    const float* W_out  = (const float*)d_in[6];
    const float* b_out  = (const float*)d_in[7];
    float* out = (float*)d_out;

    static int smem_set = 0;
    if (!smem_set) {
        cudaFuncSetAttribute(gnn_main8, cudaFuncAttributeMaxDynamicSharedMemorySize, SMEM_BYTES);
        smem_set = 1;
    }

    prep_pq<<<256, 256>>>(nodes, W_in, b_in);
    conv_w3<<<dim3(8, 8), 256>>>(W_in);
    prefetch_edges<<<148, 256>>>(edges);
    gnn_main8<<<1024, 256, SMEM_BYTES>>>(edges, W_coef, out);
    finalize3<<<dim3(2, 128), 256>>>(nodes, W_out, b_out, out);
}

// round 16
// speedup vs baseline: 1.1646x; 1.1646x over previous
#include <cuda_runtime.h>
#include <cuda_fp16.h>
#include <cstdint>

// Shapes fixed: B=16, N=64, D=E=256. Output: [new_nodes 1024x256 | h 65536x256] f32.
#define NROWS     1024
#define OUT_H_OFF (NROWS * 256)

// ---------------- device scratch ----------------
__device__ float    g_PQ[NROWS * 512];    // P = nodes@W1 + b_in | Q = nodes@W2
__device__ uint32_t g_W3p[128 * 256];     // W3 fp16 k-pair packed: [kp][n]
__device__ float    g_res[NROWS * 256];   // attn-weighted residual

// ---------------- helpers ----------------
__device__ __forceinline__ uint32_t pack2h(float lo, float hi) {
    __half2 h = __floats2half2_rn(lo, hi);
    return *(uint32_t*)&h;
}
__device__ __forceinline__ void mma_f16(float* c, const uint32_t* a, const uint32_t* b) {
    asm volatile(
        "mma.sync.aligned.m16n8k16.row.col.f32.f16.f16.f32 "
        "{%0,%1,%2,%3}, {%4,%5,%6,%7}, {%8,%9}, {%0,%1,%2,%3};"
        : "+f"(c[0]), "+f"(c[1]), "+f"(c[2]), "+f"(c[3])
        : "r"(a[0]), "r"(a[1]), "r"(a[2]), "r"(a[3]), "r"(b[0]), "r"(b[1]));
}
__device__ __forceinline__ uint32_t smem_u32(const void* p) {
    uint32_t a;
    asm("{ .reg .u64 t; cvta.to.shared.u64 t, %1; cvt.u32.u64 %0, t; }" : "=r"(a) : "l"(p));
    return a;
}
#define CP_ASYNC16(dst, src) \
    asm volatile("cp.async.cg.shared.global [%0], [%1], 16;" :: "r"(dst), "l"(src))
#define CP_COMMIT()  asm volatile("cp.async.commit_group;" ::: "memory")
#define CP_WAIT1()   asm volatile("cp.async.wait_group 1;" ::: "memory")
#define CP_WAIT0()   asm volatile("cp.async.wait_group 0;" ::: "memory")

// ---------------- smem layout for gnn_main7 (bytes, R13-exact) ----------------
#define ESM_OFF   0        // E tile fp16 [64][40] halves = 5120
#define WC0_OFF   5120     // [16][264] u32 = 16896 -> 22016
#define WC1_OFF   22016    // -> 38912
#define HS_OFF    0        // epilogue overlay [64][260] f = 66560
#define PS_OFF    66560    // 256 f
#define WCS_OFF   67584    // 256 f
#define CP_OFF    68608    // [4][64] f
#define COEF_OFF  69632    // 64 f
#define ATTN_OFF  69888    // 64 f
#define SMEM_BYTES 70144

// ===========================================================================
// Kernel A: blocks 0..127 -> PQ via fp16 mma (CTA tile 64 rows x 64 cols,
// warp tile 16x32, K=256 in 8 chunks of 32; R13-proven fragment mapping);
// blocks 128..159 -> W3 fp16 k-pair pack. grid 160 x 256.
// ===========================================================================
__global__ __launch_bounds__(256) void prep9(
    const float* __restrict__ nodes, const float* __restrict__ W_in, const float* __restrict__ b_in)
{
    __shared__ uint32_t Asm[64 * 20];   // A fp16 [64 rows][20 u32] (40 halves, 80B stride)
    __shared__ uint32_t Wsm[16 * 72];   // W fp16 packed [16 kp][72 u32 stride] (64 used)

    const int tid = threadIdx.x;

    if (blockIdx.x >= 128) {
        // ---- W3 -> packed fp16 [kp][n] (for gnn) ----
        const float* W3 = W_in + (size_t)512 * 256;
#pragma unroll
        for (int u = 0; u < 4; ++u) {
            int o = (blockIdx.x - 128) * 1024 + u * 256 + tid;   // 0..32767
            int kp = o >> 8, n = o & 255;
            g_W3p[o] = pack2h(W3[(size_t)(2 * kp) * 256 + n],
                              W3[(size_t)(2 * kp + 1) * 256 + n]);
        }
        return;
    }

    const int cb = blockIdx.x & 7;          // 0..7: col block of PQ (64 cols)
    const int rb = blockIdx.x >> 3;         // 0..15: row block (64 rows)
    const int wrow = (cb >= 4) ? 256 : 0;   // W_in f32 row base (W1 or W2)
    const int nbase = (cb & 3) * 64;        // col base within W block
    const int wid = tid >> 5;
    const int l   = tid & 31;
    const int mw  = wid >> 1;               // 0..3: m-tile (16 rows)
    const int nw  = wid & 1;                // 0..1: n-tile (32 cols)
    const int rg  = l >> 2;
    const int tg  = l & 3;

    // ---- A staging: nodes rows rb*64.., LDG f32 -> fp16 pack -> STS ----
    const int er = tid >> 2;                // 0..63
    const int ek = (tid & 3) * 8;           // halves offset
    float4 apf0, apf1;
    auto loadA = [&](int ch) {
        const float* p = nodes + (size_t)(rb * 64 + er) * 256 + ch * 32 + ek;
        apf0 = *(const float4*)p;
        apf1 = *(const float4*)(p + 4);
    };
    auto stsA = [&]() {
        uint4 u;
        u.x = pack2h(apf0.x, apf0.y);
        u.y = pack2h(apf0.z, apf0.w);
        u.z = pack2h(apf1.x, apf1.y);
        u.w = pack2h(apf1.z, apf1.w);
        *(uint4*)((char*)Asm + er * 80 + ek * 2) = u;
    };

    // ---- W staging: 16 kp x 64 n per chunk, LDG f32 x2 -> pack -> STS ----
    float wlo[4], whi[4];
    auto loadW = [&](int ch) {
#pragma unroll
        for (int u = 0; u < 4; ++u) {
            int idx = tid + u * 256;            // 0..1023
            int kp = idx >> 6, n = idx & 63;
            int row = wrow + ch * 32 + 2 * kp;
            wlo[u] = W_in[(size_t)row * 256 + nbase + n];
            whi[u] = W_in[(size_t)(row + 1) * 256 + nbase + n];
        }
    };
    auto stsW = [&]() {
#pragma unroll
        for (int u = 0; u < 4; ++u) {
            int idx = tid + u * 256;
            int kp = idx >> 6, n = idx & 63;
            Wsm[kp * 72 + n] = pack2h(wlo[u], whi[u]);
        }
    };

    float acc[4][4];
#pragma unroll
    for (int nt = 0; nt < 4; ++nt)
#pragma unroll
        for (int q = 0; q < 4; ++q) acc[nt][q] = 0.f;

    loadA(0);
    loadW(0);

    for (int ch = 0; ch < 8; ++ch) {
        stsA();
        stsW();
        __syncthreads();

        if (ch < 7) { loadA(ch + 1); loadW(ch + 1); }

#pragma unroll
        for (int s = 0; s < 2; ++s) {
            const int kh = s * 8;               // u32 (k-pair) base within chunk
            uint32_t a[4], b[4][2];
            int r0 = mw * 16 + rg;
            a[0] = Asm[r0 * 20 + kh + tg];
            a[1] = Asm[(r0 + 8) * 20 + kh + tg];
            a[2] = Asm[r0 * 20 + kh + tg + 4];
            a[3] = Asm[(r0 + 8) * 20 + kh + tg + 4];
            const uint32_t* Wk0 = Wsm + (kh + tg) * 72;
            const uint32_t* Wk1 = Wsm + (kh + tg + 4) * 72;
#pragma unroll
            for (int nt = 0; nt < 4; ++nt) {
                int n0 = nw * 32 + nt * 8 + rg;
                b[nt][0] = Wk0[n0];
                b[nt][1] = Wk1[n0];
            }
#pragma unroll
            for (int nt = 0; nt < 4; ++nt)
                mma_f16(acc[nt], a, b[nt]);
        }
        __syncthreads();
    }

    // ---- epilogue: write g_PQ (+ b_in for P half) ----
    const int rA = rb * 64 + mw * 16 + rg;
    const int rB = rA + 8;
#pragma unroll
    for (int nt = 0; nt < 4; ++nt) {
        int c = cb * 64 + nw * 32 + nt * 8 + tg * 2;
        float bx = 0.f, by = 0.f;
        if (cb < 4) { float2 bv = *(const float2*)(b_in + c); bx = bv.x; by = bv.y; }
        *(float2*)(g_PQ + (size_t)rA * 512 + c) = make_float2(acc[nt][0] + bx, acc[nt][1] + by);
        *(float2*)(g_PQ + (size_t)rB * 512 + c) = make_float2(acc[nt][2] + bx, acc[nt][3] + by);
    }
}

// ===========================================================================
// Kernel B: fp16 m16n8k16 mma GEMM + fused attention. (R13-exact)
// ===========================================================================
__global__ __launch_bounds__(256) void gnn_main7(
    const float* __restrict__ edges,
    const float* __restrict__ W_coef,
    float* __restrict__ out)
{
    extern __shared__ char sm[];
    const uint32_t sbase = smem_u32(sm);
    float* hs   = (float*)(sm + HS_OFF);
    float* ps   = (float*)(sm + PS_OFF);
    float* wcs  = (float*)(sm + WCS_OFF);
    float* cp   = (float*)(sm + CP_OFF);
    float* coef_s = (float*)(sm + COEF_OFF);
    float* attn_s = (float*)(sm + ATTN_OFF);

    const int tid = threadIdx.x;
    const int wid = tid >> 5;
    const int l   = tid & 31;
    const int mw  = wid >> 2;
    const int nw  = wid & 3;
    const int rg  = l >> 2;
    const int tg  = l & 3;
    const int bid = blockIdx.x;
    const int b64 = (bid >> 6) << 6;
    const int i_g = bid & 63;

    ps[tid]  = g_PQ[(size_t)bid * 512 + tid];
    wcs[tid] = W_coef[tid];

    const float* Ebase = edges + (size_t)bid * 64 * 256;

    const int er = tid >> 2;
    const int ek = (tid & 3) * 8;
    float4 epf0, epf1;
    auto loadE = [&](int ch) {
        const float* p = Ebase + (size_t)er * 256 + ch * 32 + ek;
        epf0 = *(const float4*)p;
        epf1 = *(const float4*)(p + 4);
    };
    auto stsE = [&]() {
        uint4 u;
        u.x = pack2h(epf0.x, epf0.y);
        u.y = pack2h(epf0.z, epf0.w);
        u.z = pack2h(epf1.x, epf1.y);
        u.w = pack2h(epf1.z, epf1.w);
        *(uint4*)(sm + ESM_OFF + (er * 40 + ek) * 2) = u;
    };

    auto stageW = [&](int ch, int buf) {
        uint32_t w_dst = sbase + (buf ? WC1_OFF : WC0_OFF);
#pragma unroll
        for (int u = 0; u < 4; ++u) {
            int idx = tid + u * 256;
            int kp = idx >> 6, n4 = (idx & 63) << 2;
            CP_ASYNC16(w_dst + (uint32_t)(kp * 264 + n4) * 4,
                       g_W3p + (size_t)(ch * 16 + kp) * 256 + n4);
        }
    };

    float acc[2][8][4];
#pragma unroll
    for (int mt = 0; mt < 2; ++mt)
#pragma unroll
        for (int nt = 0; nt < 8; ++nt)
#pragma unroll
            for (int q = 0; q < 4; ++q) acc[mt][nt][q] = 0.f;

    loadE(0);
    stageW(0, 0);
    CP_COMMIT();

    for (int ch = 0; ch < 8; ++ch) {
        stsE();
        if (ch < 7) {
            stageW(ch + 1, (ch + 1) & 1);
            CP_COMMIT();
            CP_WAIT1();
        } else {
            CP_WAIT0();
        }
        __syncthreads();

        if (ch < 7) loadE(ch + 1);

        const uint32_t* EchU = (const uint32_t*)(sm + ESM_OFF);
        const uint32_t* WchU = (const uint32_t*)(sm + ((ch & 1) ? WC1_OFF : WC0_OFF));

#pragma unroll
        for (int s = 0; s < 2; ++s) {
            const int kh = s * 8;
            uint32_t a[2][4], b[8][2];
#pragma unroll
            for (int mt = 0; mt < 2; ++mt) {
                int r0 = mw * 32 + mt * 16 + rg;
                a[mt][0] = EchU[r0 * 20 + kh + tg];
                a[mt][1] = EchU[(r0 + 8) * 20 + kh + tg];
                a[mt][2] = EchU[r0 * 20 + kh + tg + 4];
                a[mt][3] = EchU[(r0 + 8) * 20 + kh + tg + 4];
            }
            const uint32_t* Wk0 = WchU + (kh + tg) * 264;
            const uint32_t* Wk1 = WchU + (kh + tg + 4) * 264;
#pragma unroll
            for (int nt = 0; nt < 8; ++nt) {
                int n0 = nw * 64 + nt * 8 + rg;
                b[nt][0] = Wk0[n0];
                b[nt][1] = Wk1[n0];
            }
#pragma unroll
            for (int mt = 0; mt < 2; ++mt)
#pragma unroll
                for (int nt = 0; nt < 8; ++nt)
                    mma_f16(acc[mt][nt], a[mt], b[nt]);
        }
        __syncthreads();
    }

    // ---- epilogue: h = relu(acc + P_i + Q_j) -> hs ----
#pragma unroll
    for (int mt = 0; mt < 2; ++mt) {
        int rA = mw * 32 + mt * 16 + rg;
        int rB = rA + 8;
        const float* qA = g_PQ + (size_t)(b64 + rA) * 512 + 256;
        const float* qB = g_PQ + (size_t)(b64 + rB) * 512 + 256;
#pragma unroll
        for (int nt = 0; nt < 8; ++nt) {
            int c0 = nw * 64 + nt * 8 + tg * 2;
            float2 pv = *(const float2*)(ps + c0);
            float2 qa = *(const float2*)(qA + c0);
            float2 qb = *(const float2*)(qB + c0);
            float h0 = fmaxf(acc[mt][nt][0] + pv.x + qa.x, 0.f);
            float h1 = fmaxf(acc[mt][nt][1] + pv.y + qa.y, 0.f);
            float h2 = fmaxf(acc[mt][nt][2] + pv.x + qb.x, 0.f);
            float h3 = fmaxf(acc[mt][nt][3] + pv.y + qb.y, 0.f);
            *(float2*)(hs + rA * 260 + c0) = make_float2(h0, h1);
            *(float2*)(hs + rB * 260 + c0) = make_float2(h2, h3);
        }
    }
    __syncthreads();

    // ---- h -> gmem ----
    float* hout = out + OUT_H_OFF + (size_t)bid * 64 * 256;
#pragma unroll
    for (int rr = wid * 8; rr < wid * 8 + 8; ++rr) {
#pragma unroll
        for (int q = 0; q < 2; ++q) {
            float4 v = *(const float4*)(hs + rr * 260 + q * 128 + l * 4);
            *(float4*)(hout + (size_t)rr * 256 + q * 128 + l * 4) = v;
        }
    }

    // ---- coef[j] = sum_d h[j][d] * wc[d] ----
    {
        int j = tid & 63, seg = tid >> 6;
        float s = 0.f;
#pragma unroll 8
        for (int d = 0; d < 64; ++d)
            s += hs[j * 260 + seg * 64 + d] * wcs[seg * 64 + d];
        cp[seg * 64 + j] = s;
    }
    __syncthreads();
    if (tid < 64)
        coef_s[tid] = cp[tid] + cp[64 + tid] + cp[128 + tid] + cp[192 + tid]
                    - ((tid == i_g) ? 1e9f : 0.f);
    __syncthreads();

    // ---- softmax ----
    float mval = -3.0e38f;
#pragma unroll 8
    for (int j = 0; j < 64; ++j) mval = fmaxf(mval, coef_s[j]);
    if (tid < 64) attn_s[tid] = __expf(coef_s[tid] - mval);
    __syncthreads();

    float ssum = 0.f;
#pragma unroll 8
    for (int j = 0; j < 64; ++j) ssum += attn_s[j];
    float inv = 1.f / ssum;

    // ---- residual ----
    float r = 0.f;
#pragma unroll 8
    for (int j = 0; j < 64; ++j)
        r += attn_s[j] * hs[j * 260 + tid];
    g_res[(size_t)bid * 256 + tid] = r * inv;
}

// ===========================================================================
// Kernel C: new_nodes = nodes + relu(g_res @ W_out + b_out). (unchanged)
// ===========================================================================
__global__ __launch_bounds__(256) void finalize3(
    const float* __restrict__ nodes, const float* __restrict__ W_out,
    const float* __restrict__ b_out, float* __restrict__ out)
{
    __shared__ float rs[8 * 256];
    __shared__ float red[8 * 128];
    const int tid = threadIdx.x;
    const int c0 = blockIdx.x * 128;
    const int r0 = blockIdx.y * 8;
    const int lc = tid & 127;
    const int c  = c0 + lc;
    const int kh = tid >> 7;

#pragma unroll
    for (int u = 0; u < 8; ++u)
        rs[u * 256 + tid] = g_res[(size_t)(r0 + u) * 256 + tid];
    __syncthreads();

    float acc[8];
#pragma unroll
    for (int q = 0; q < 8; ++q) acc[q] = 0.f;

    const int kbase = kh * 128;
    const float* Wp = W_out + (size_t)kbase * 256 + c;

#pragma unroll 8
    for (int k4 = 0; k4 < 32; ++k4) {
        float w0 = Wp[(size_t)(k4 * 4 + 0) * 256];
        float w1 = Wp[(size_t)(k4 * 4 + 1) * 256];
        float w2 = Wp[(size_t)(k4 * 4 + 2) * 256];
        float w3 = Wp[(size_t)(k4 * 4 + 3) * 256];
#pragma unroll
        for (int q = 0; q < 8; ++q) {
            float4 rv = *(const float4*)(rs + q * 256 + kbase + k4 * 4);
            acc[q] += rv.x * w0 + rv.y * w1 + rv.z * w2 + rv.w * w3;
        }
    }

    if (kh) {
#pragma unroll
        for (int q = 0; q < 8; ++q) red[q * 128 + lc] = acc[q];
    }
    __syncthreads();
    if (!kh) {
        float bo = b_out[c];
#pragma unroll
        for (int q = 0; q < 8; ++q) {
            float v = acc[q] + red[q * 128 + lc] + bo;
            out[(size_t)(r0 + q) * 256 + c] =
                nodes[(size_t)(r0 + q) * 256 + c] + fmaxf(v, 0.f);
        }
    }
}

// ===========================================================================
extern "C" void kernel_launch(void* const* d_in, const int* in_sizes, int n_in,
                              void* d_out, int out_size) {
    const float* nodes  = (const float*)d_in[0];
    const float* edges  = (const float*)d_in[1];
    const float* W_in   = (const float*)d_in[2];
    const float* b_in   = (const float*)d_in[3];
    const float* W_coef = (const float*)d_in[4];
    // d_in[5] = b_coef: softmax-invariant, skipped
    const float* W_out  = (const float*)d_in[6];
    const float* b_out  = (const float*)d_in[7];
    float* out = (float*)d_out;

    static int smem_set = 0;
    if (!smem_set) {
        cudaFuncSetAttribute(gnn_main7, cudaFuncAttributeMaxDynamicSharedMemorySize, SMEM_BYTES);
        smem_set = 1;
    }

    prep9<<<160, 256>>>(nodes, W_in, b_in);
    gnn_main7<<<1024, 256, SMEM_BYTES>>>(edges, W_coef, out);
    finalize3<<<dim3(2, 128), 256>>>(nodes, W_out, b_out, out);
}